// round 2
// baseline (speedup 1.0000x reference)
#include <cuda_runtime.h>
#include <math_constants.h>

#define SEQ    2048
#define BATCH  2
#define HEADS  16
#define DHEAD  64
#define DMODEL 1024
#define MROWS  (BATCH*SEQ)   // 4096

// Scratch (allocation-free rule: __device__ globals)
__device__ float g_Q[BATCH*HEADS*SEQ*DHEAD];
__device__ float g_K[BATCH*HEADS*SEQ*DHEAD];
__device__ float g_V[BATCH*HEADS*SEQ*DHEAD];
__device__ float g_O[BATCH*SEQ*DMODEL];

// ---------------------------------------------------------------------------
// SGEMM: C = A @ W^T (+bias).  A[M,K] row-major, W[N,K] row-major.
// M=4096, N=1024, K=1024. Tile 128x128x16, 256 threads, 8x8 per thread.
// MODE 0: C[m*DMODEL+n] = acc + bias[n]
// MODE 1: scatter into [B,H,S,Dh]: m->(b,s), n->(h,d)
// ---------------------------------------------------------------------------
template<int MODE>
__global__ __launch_bounds__(256)
void sgemm_kernel(const float* __restrict__ A, const float* __restrict__ W,
                  float* __restrict__ C, const float* __restrict__ bias, int K)
{
    __shared__ float As[16][132];   // +4 pad: conflict-free transposed stores/loads
    __shared__ float Bs[16][132];

    const int tid = threadIdx.x;
    const int tx  = tid & 15;
    const int ty  = tid >> 4;
    const int bm  = blockIdx.y * 128;
    const int bn  = blockIdx.x * 128;

    float acc[8][8];
#pragma unroll
    for (int i = 0; i < 8; i++)
#pragma unroll
        for (int j = 0; j < 8; j++) acc[i][j] = 0.f;

    const int lrow = tid >> 2;   // 0..63
    const int lc4  = tid & 3;    // which float4 within the 16-wide k slab

    for (int k0 = 0; k0 < K; k0 += 16) {
#pragma unroll
        for (int t = 0; t < 2; t++) {
            int row = lrow + t * 64;
            float4 va = *(const float4*)&A[(size_t)(bm + row) * K + k0 + lc4 * 4];
            As[lc4*4+0][row] = va.x; As[lc4*4+1][row] = va.y;
            As[lc4*4+2][row] = va.z; As[lc4*4+3][row] = va.w;
            float4 vb = *(const float4*)&W[(size_t)(bn + row) * K + k0 + lc4 * 4];
            Bs[lc4*4+0][row] = vb.x; Bs[lc4*4+1][row] = vb.y;
            Bs[lc4*4+2][row] = vb.z; Bs[lc4*4+3][row] = vb.w;
        }
        __syncthreads();
#pragma unroll
        for (int kk = 0; kk < 16; kk++) {
            float4 a0 = *(const float4*)&As[kk][ty * 4];
            float4 a1 = *(const float4*)&As[kk][64 + ty * 4];
            float4 b0 = *(const float4*)&Bs[kk][tx * 4];
            float4 b1 = *(const float4*)&Bs[kk][64 + tx * 4];
            float a[8] = {a0.x,a0.y,a0.z,a0.w,a1.x,a1.y,a1.z,a1.w};
            float b[8] = {b0.x,b0.y,b0.z,b0.w,b1.x,b1.y,b1.z,b1.w};
#pragma unroll
            for (int i = 0; i < 8; i++)
#pragma unroll
                for (int j = 0; j < 8; j++)
                    acc[i][j] = fmaf(a[i], b[j], acc[i][j]);
        }
        __syncthreads();
    }

#pragma unroll
    for (int i = 0; i < 8; i++) {
        int r = bm + ((i < 4) ? (ty * 4 + i) : (64 + ty * 4 + i - 4));
#pragma unroll
        for (int jg = 0; jg < 2; jg++) {
            int c = bn + jg * 64 + tx * 4;
            float4 v;
            v.x = acc[i][jg*4+0]; v.y = acc[i][jg*4+1];
            v.z = acc[i][jg*4+2]; v.w = acc[i][jg*4+3];
            if (MODE == 0) {
                if (bias) {
                    v.x += bias[c+0]; v.y += bias[c+1];
                    v.z += bias[c+2]; v.w += bias[c+3];
                }
                *(float4*)&C[(size_t)r * DMODEL + c] = v;
            } else {
                int b = r >> 11;        // r / 2048
                int s = r & 2047;
                int h = c >> 6;         // c / 64
                int d = c & 63;
                *(float4*)&C[(((size_t)(b * HEADS + h)) * SEQ + s) * DHEAD + d] = v;
            }
        }
    }
}

// ---------------------------------------------------------------------------
// Fused flash-style attention (no 1/sqrt(d) scaling, per reference).
// One CTA = (b, h, 64 queries). 256 threads as 16x16; thread (ty,tx) owns
// rows ty*4..+3 and cols tx*4..+3 of every 64x64 tile.
// Smem: Q, K(reused as P), V; 64 rows x 16 float4, swizzled:
//   slot(row,d4) = row*16 + ((d4 + row/4) & 15)   -> conflict-free LDS.128
// ---------------------------------------------------------------------------
__device__ __forceinline__ int swz(int row, int d4) {
    return row * 16 + ((d4 + (row >> 2)) & 15);
}

__global__ __launch_bounds__(256)
void attn_kernel(float* __restrict__ O)
{
    __shared__ float4 Qs[1024];   // 16 KB each; 48 KB total
    __shared__ float4 Ks[1024];   // reused as P after scores consumed
    __shared__ float4 Vs[1024];

    const int q0  = blockIdx.x * 64;
    const int h   = blockIdx.y;
    const int b   = blockIdx.z;
    const int tid = threadIdx.x;
    const int tx  = tid & 15;
    const int ty  = tid >> 4;

    const size_t base = ((size_t)(b * HEADS + h)) * SEQ * DHEAD;
    const float4* Qg = (const float4*)(g_Q + base);
    const float4* Kg = (const float4*)(g_K + base);
    const float4* Vg = (const float4*)(g_V + base);

#pragma unroll
    for (int t = 0; t < 4; t++) {
        int f = tid + t * 256;
        int row = f >> 4, d4 = f & 15;
        Qs[swz(row, d4)] = Qg[(q0 + row) * 16 + d4];
    }

    float  m_prev[4], l[4];
    float4 o4[4];
#pragma unroll
    for (int i = 0; i < 4; i++) {
        m_prev[i] = -CUDART_INF_F;
        l[i] = 0.f;
        o4[i] = make_float4(0.f, 0.f, 0.f, 0.f);
    }

    for (int kt = 0; kt < SEQ / 64; kt++) {
        const int k0 = kt * 64;
        __syncthreads();   // previous tile's P/V fully consumed (also covers Q store)
#pragma unroll
        for (int t = 0; t < 4; t++) {
            int f = tid + t * 256;
            int row = f >> 4, d4 = f & 15;
            Ks[swz(row, d4)] = Kg[(k0 + row) * 16 + d4];
            Vs[swz(row, d4)] = Vg[(k0 + row) * 16 + d4];
        }
        __syncthreads();

        // S = Q @ K^T   (64x64 tile, unscaled)
        float s[4][4];
#pragma unroll
        for (int i = 0; i < 4; i++)
#pragma unroll
            for (int j = 0; j < 4; j++) s[i][j] = 0.f;

#pragma unroll
        for (int d4 = 0; d4 < 16; d4++) {
            float4 qv[4], kv[4];
#pragma unroll
            for (int i = 0; i < 4; i++) qv[i] = Qs[swz(ty * 4 + i, d4)];
#pragma unroll
            for (int j = 0; j < 4; j++) kv[j] = Ks[swz(tx * 4 + j, d4)];
#pragma unroll
            for (int i = 0; i < 4; i++)
#pragma unroll
                for (int j = 0; j < 4; j++)
                    s[i][j] += qv[i].x * kv[j].x + qv[i].y * kv[j].y
                             + qv[i].z * kv[j].z + qv[i].w * kv[j].w;
        }

        // online softmax (row reductions across the 16 tx-lanes of this warp half)
        float p[4][4];
#pragma unroll
        for (int i = 0; i < 4; i++) {
            float rmax = fmaxf(fmaxf(s[i][0], s[i][1]), fmaxf(s[i][2], s[i][3]));
#pragma unroll
            for (int off = 8; off >= 1; off >>= 1)
                rmax = fmaxf(rmax, __shfl_xor_sync(0xffffffffu, rmax, off));
            float mnew  = fmaxf(m_prev[i], rmax);
            float alpha = __expf(m_prev[i] - mnew);
            float rsum  = 0.f;
#pragma unroll
            for (int j = 0; j < 4; j++) {
                p[i][j] = __expf(s[i][j] - mnew);
                rsum += p[i][j];
            }
#pragma unroll
            for (int off = 8; off >= 1; off >>= 1)
                rsum += __shfl_xor_sync(0xffffffffu, rsum, off);
            l[i] = l[i] * alpha + rsum;
            m_prev[i] = mnew;
            o4[i].x *= alpha; o4[i].y *= alpha; o4[i].z *= alpha; o4[i].w *= alpha;
        }

        __syncthreads();   // everyone done reading Ks before overwrite with P
#pragma unroll
        for (int i = 0; i < 4; i++)
            Ks[swz(ty * 4 + i, tx)] = make_float4(p[i][0], p[i][1], p[i][2], p[i][3]);
        __syncthreads();

        // O += P @ V
#pragma unroll
        for (int k4 = 0; k4 < 16; k4++) {
            float4 pv[4], vv[4];
#pragma unroll
            for (int i = 0; i < 4; i++)  pv[i] = Ks[swz(ty * 4 + i, k4)];
#pragma unroll
            for (int kk = 0; kk < 4; kk++) vv[kk] = Vs[swz(k4 * 4 + kk, tx)];
#pragma unroll
            for (int i = 0; i < 4; i++) {
                o4[i].x += pv[i].x*vv[0].x + pv[i].y*vv[1].x + pv[i].z*vv[2].x + pv[i].w*vv[3].x;
                o4[i].y += pv[i].x*vv[0].y + pv[i].y*vv[1].y + pv[i].z*vv[2].y + pv[i].w*vv[3].y;
                o4[i].z += pv[i].x*vv[0].z + pv[i].y*vv[1].z + pv[i].z*vv[2].z + pv[i].w*vv[3].z;
                o4[i].w += pv[i].x*vv[0].w + pv[i].y*vv[1].w + pv[i].z*vv[2].w + pv[i].w*vv[3].w;
            }
        }
    }

    // normalize + write in [B,S,D] layout
#pragma unroll
    for (int i = 0; i < 4; i++) {
        float inv = 1.f / l[i];
        int q = q0 + ty * 4 + i;
        float4 v = make_float4(o4[i].x * inv, o4[i].y * inv, o4[i].z * inv, o4[i].w * inv);
        *(float4*)&O[((size_t)b * SEQ + q) * DMODEL + h * DHEAD + tx * 4] = v;
    }
}

// ---------------------------------------------------------------------------
// Launch: 3 projection GEMMs -> fused attention -> output GEMM (+bias)
// ---------------------------------------------------------------------------
extern "C" void kernel_launch(void* const* d_in, const int* in_sizes, int n_in,
                              void* d_out, int out_size)
{
    const float* x  = (const float*)d_in[0];
    // d_in[1] = attn_weights (unused by reference forward)
    const float* Wq = (const float*)d_in[2];
    const float* Wk = (const float*)d_in[3];
    const float* Wv = (const float*)d_in[4];
    const float* Wp = (const float*)d_in[5];
    const float* bp = (const float*)d_in[6];
    float* out = (float*)d_out;

    float *Qp, *Kp, *Vp, *Op;
    cudaGetSymbolAddress((void**)&Qp, g_Q);
    cudaGetSymbolAddress((void**)&Kp, g_K);
    cudaGetSymbolAddress((void**)&Vp, g_V);
    cudaGetSymbolAddress((void**)&Op, g_O);

    dim3 gg(DMODEL / 128, MROWS / 128);   // (8, 32)
    sgemm_kernel<1><<<gg, 256>>>(x, Wq, Qp, nullptr, DMODEL);
    sgemm_kernel<1><<<gg, 256>>>(x, Wk, Kp, nullptr, DMODEL);
    sgemm_kernel<1><<<gg, 256>>>(x, Wv, Vp, nullptr, DMODEL);

    attn_kernel<<<dim3(SEQ / 64, HEADS, BATCH), 256>>>(Op);

    sgemm_kernel<0><<<gg, 256>>>(Op, Wp, out, bp, DMODEL);
}

// round 4
// speedup vs baseline: 1.3750x; 1.3750x over previous
#include <cuda_runtime.h>
#include <cuda_bf16.h>
#include <math_constants.h>
#include <cstdint>

#define SEQ    2048
#define BATCH  2
#define HEADS  16
#define DHEAD  64
#define DMODEL 1024
#define MROWS  (BATCH*SEQ)   // 4096

// ---------------------------------------------------------------------------
// Scratch (__device__ globals: allocation-free rule)
// ---------------------------------------------------------------------------
__device__ float g_Q[BATCH*HEADS*SEQ*DHEAD];
__device__ float g_K[BATCH*HEADS*SEQ*DHEAD];
__device__ float g_V[BATCH*HEADS*SEQ*DHEAD];
__device__ float g_O[BATCH*SEQ*DMODEL];
__device__ __nv_bfloat16 g_xh[MROWS*DMODEL], g_xl[MROWS*DMODEL];
__device__ __nv_bfloat16 g_Wh[4*DMODEL*DMODEL], g_Wl[4*DMODEL*DMODEL]; // q,k,v,p
__device__ __nv_bfloat16 g_Oh[MROWS*DMODEL], g_Ol[MROWS*DMODEL];

// ---------------------------------------------------------------------------
// PTX helpers (compute_103-safe: cp.async + ldmatrix + mma.sync only)
// ---------------------------------------------------------------------------
__device__ __forceinline__ uint32_t smem_u32(const void* p) {
    uint32_t a;
    asm("{ .reg .u64 t; cvta.to.shared.u64 t, %1; cvt.u32.u64 %0, t; }" : "=r"(a) : "l"(p));
    return a;
}
#define CP16(dst, src)  asm volatile("cp.async.cg.shared.global [%0], [%1], 16;" :: "r"(dst), "l"(src))
#define CP_COMMIT()     asm volatile("cp.async.commit_group;" ::: "memory")
#define CP_WAIT0()      asm volatile("cp.async.wait_group 0;" ::: "memory")
#define CP_WAIT1()      asm volatile("cp.async.wait_group 1;" ::: "memory")

__device__ __forceinline__ void ldm_x4(uint32_t (&r)[4], uint32_t addr) {
    asm volatile("ldmatrix.sync.aligned.m8n8.x4.shared.b16 {%0,%1,%2,%3}, [%4];"
        : "=r"(r[0]), "=r"(r[1]), "=r"(r[2]), "=r"(r[3]) : "r"(addr));
}
__device__ __forceinline__ void ldm_x2(uint32_t (&r)[2], uint32_t addr) {
    asm volatile("ldmatrix.sync.aligned.m8n8.x2.shared.b16 {%0,%1}, [%2];"
        : "=r"(r[0]), "=r"(r[1]) : "r"(addr));
}
__device__ __forceinline__ void mma_bf16(float (&c)[4], const uint32_t (&a)[4], const uint32_t (&b)[2]) {
    asm volatile("mma.sync.aligned.m16n8k16.row.col.f32.bf16.bf16.f32 "
        "{%0,%1,%2,%3}, {%4,%5,%6,%7}, {%8,%9}, {%0,%1,%2,%3};"
        : "+f"(c[0]), "+f"(c[1]), "+f"(c[2]), "+f"(c[3])
        : "r"(a[0]), "r"(a[1]), "r"(a[2]), "r"(a[3]), "r"(b[0]), "r"(b[1]));
}

// ---------------------------------------------------------------------------
// Split fp32 -> (bf16 hi, bf16 lo)
// ---------------------------------------------------------------------------
__global__ void split_kernel(const float4* __restrict__ in, __nv_bfloat162* __restrict__ hi,
                             __nv_bfloat162* __restrict__ lo, int n4)
{
    int i = blockIdx.x * blockDim.x + threadIdx.x;
    if (i >= n4) return;
    float4 v = in[i];
    __nv_bfloat162 h0 = __floats2bfloat162_rn(v.x, v.y);
    __nv_bfloat162 h1 = __floats2bfloat162_rn(v.z, v.w);
    hi[2*i]   = h0;
    hi[2*i+1] = h1;
    float rx = v.x - __bfloat162float(h0.x);
    float ry = v.y - __bfloat162float(h0.y);
    float rz = v.z - __bfloat162float(h1.x);
    float rw = v.w - __bfloat162float(h1.y);
    lo[2*i]   = __floats2bfloat162_rn(rx, ry);
    lo[2*i+1] = __floats2bfloat162_rn(rz, rw);
}

// ---------------------------------------------------------------------------
// mma.sync split-bf16 GEMM: C[M,N] = A[M,K] @ B[N,K]^T  (fp32-grade accuracy)
// CTA 128x128, 8 warps (2x4), warp 64x32. K-chunks of 64, 2-stage cp.async.
// smem tile rows padded to 72 bf16 (144 B) -> conflict-free ldmatrix.
// MODE 0: C[r*DMODEL+c] = acc + bias[c];  MODE 1: scatter into [B,H,S,Dh].
// ---------------------------------------------------------------------------
template<int MODE>
__global__ __launch_bounds__(256)
void mma_gemm(const __nv_bfloat16* __restrict__ Ah, const __nv_bfloat16* __restrict__ Al,
              const __nv_bfloat16* __restrict__ Bh, const __nv_bfloat16* __restrict__ Bl,
              float* __restrict__ C, const float* __restrict__ bias)
{
    constexpr int K = DMODEL;
    constexpr int BK = 64;
    constexpr int NCHUNK = K / BK;            // 16
    constexpr int RSTRIDE = 144;              // bytes per smem row (72 bf16)
    constexpr int TILE = 128 * RSTRIDE;       // 18432 B
    constexpr int STAGE = 4 * TILE;           // Ah, Al, Bh, Bl

    extern __shared__ __align__(128) char smem[];
    const uint32_t sb = smem_u32(smem);
    const int tid  = threadIdx.x;
    const int wid  = tid >> 5;
    const int lane = tid & 31;
    const int warp_m = wid & 1;               // 2 x 64 rows
    const int warp_n = wid >> 1;              // 4 x 32 cols
    const int bm = blockIdx.y * 128;
    const int bn = blockIdx.x * 128;

    // per-thread ldmatrix base offsets (bytes, within a tile)
    const uint32_t aoff = (uint32_t)(warp_m * 64 + (lane & 15)) * RSTRIDE + (uint32_t)(lane >> 4) * 16;
    const uint32_t boff = (uint32_t)(warp_n * 32 + (lane & 7))  * RSTRIDE + (uint32_t)((lane >> 3) & 1) * 16;

    float acc[4][4][4];
#pragma unroll
    for (int mi = 0; mi < 4; mi++)
#pragma unroll
        for (int ni = 0; ni < 4; ni++)
#pragma unroll
            for (int j = 0; j < 4; j++) acc[mi][ni][j] = 0.f;

    auto load_chunk = [&](int i) {
        uint32_t base = sb + (uint32_t)(i & 1) * STAGE;
        int k0 = i * BK;
#pragma unroll
        for (int t = 0; t < 4; t++) {
            int c   = tid + t * 256;          // 0..1023
            int row = c >> 3, kk = c & 7;
            uint32_t so = (uint32_t)row * RSTRIDE + (uint32_t)kk * 16;
            size_t ao = (size_t)(bm + row) * K + k0 + kk * 8;
            size_t bo = (size_t)(bn + row) * K + k0 + kk * 8;
            CP16(base + so,            Ah + ao);
            CP16(base + TILE + so,     Al + ao);
            CP16(base + 2*TILE + so,   Bh + bo);
            CP16(base + 3*TILE + so,   Bl + bo);
        }
    };

    load_chunk(0);
    CP_COMMIT();

    for (int i = 0; i < NCHUNK; i++) {
        if (i + 1 < NCHUNK) { load_chunk(i + 1); CP_COMMIT(); CP_WAIT1(); }
        else                { CP_WAIT0(); }
        __syncthreads();

        uint32_t base = sb + (uint32_t)(i & 1) * STAGE;
#pragma unroll
        for (int ks = 0; ks < 4; ks++) {
            const uint32_t koff = (uint32_t)ks * 32;   // 16 bf16 = 32 B
            uint32_t bh[4][2], bl[4][2];
#pragma unroll
            for (int ni = 0; ni < 4; ni++) {
                uint32_t ba = base + boff + (uint32_t)ni * 8 * RSTRIDE + koff;
                ldm_x2(bh[ni], ba + 2*TILE);
                ldm_x2(bl[ni], ba + 3*TILE);
            }
            uint32_t af[4][4];
#pragma unroll
            for (int mi = 0; mi < 4; mi++)
                ldm_x4(af[mi], base + aoff + (uint32_t)mi * 16 * RSTRIDE + koff);
#pragma unroll
            for (int mi = 0; mi < 4; mi++)
#pragma unroll
                for (int ni = 0; ni < 4; ni++) mma_bf16(acc[mi][ni], af[mi], bh[ni]);
#pragma unroll
            for (int mi = 0; mi < 4; mi++)
#pragma unroll
                for (int ni = 0; ni < 4; ni++) mma_bf16(acc[mi][ni], af[mi], bl[ni]);
#pragma unroll
            for (int mi = 0; mi < 4; mi++)
                ldm_x4(af[mi], base + TILE + aoff + (uint32_t)mi * 16 * RSTRIDE + koff);
#pragma unroll
            for (int mi = 0; mi < 4; mi++)
#pragma unroll
                for (int ni = 0; ni < 4; ni++) mma_bf16(acc[mi][ni], af[mi], bh[ni]);
        }
        __syncthreads();
    }

    // Epilogue: thread t holds C[row=g][c0..c0+1] and C[row=g+8][...], g = lane>>2
    const int rbase = bm + warp_m * 64 + (lane >> 2);
    const int cbase = bn + warp_n * 32 + 2 * (lane & 3);
#pragma unroll
    for (int mi = 0; mi < 4; mi++) {
#pragma unroll
        for (int ni = 0; ni < 4; ni++) {
            int c = cbase + ni * 8;
#pragma unroll
            for (int half = 0; half < 2; half++) {
                int r = rbase + mi * 16 + half * 8;
                float2 v = make_float2(acc[mi][ni][2*half], acc[mi][ni][2*half + 1]);
                if (MODE == 0) {
                    v.x += bias[c]; v.y += bias[c + 1];
                    *(float2*)&C[(size_t)r * DMODEL + c] = v;
                } else {
                    int b = r >> 11, s = r & 2047;
                    int h = c >> 6,  d = c & 63;
                    *(float2*)&C[(((size_t)(b * HEADS + h)) * SEQ + s) * DHEAD + d] = v;
                }
            }
        }
    }
}

// ---------------------------------------------------------------------------
// Fused flash-style attention (fp32 SIMT), 2 CTAs/SM
// ---------------------------------------------------------------------------
__device__ __forceinline__ int swz(int row, int d4) {
    return row * 16 + ((d4 + (row >> 2)) & 15);
}

__global__ __launch_bounds__(256, 2)
void attn_kernel(float* __restrict__ O)
{
    __shared__ float4 Qs[1024];
    __shared__ float4 Ks[1024];   // reused as P
    __shared__ float4 Vs[1024];

    const int q0  = blockIdx.x * 64;
    const int h   = blockIdx.y;
    const int b   = blockIdx.z;
    const int tid = threadIdx.x;
    const int tx  = tid & 15;
    const int ty  = tid >> 4;

    const size_t base = ((size_t)(b * HEADS + h)) * SEQ * DHEAD;
    const float4* Qg = (const float4*)(g_Q + base);
    const float4* Kg = (const float4*)(g_K + base);
    const float4* Vg = (const float4*)(g_V + base);

#pragma unroll
    for (int t = 0; t < 4; t++) {
        int f = tid + t * 256;
        int row = f >> 4, d4 = f & 15;
        Qs[swz(row, d4)] = Qg[(q0 + row) * 16 + d4];
    }

    float  m_prev[4], l[4];
    float4 o4[4];
#pragma unroll
    for (int i = 0; i < 4; i++) {
        m_prev[i] = -CUDART_INF_F;
        l[i] = 0.f;
        o4[i] = make_float4(0.f, 0.f, 0.f, 0.f);
    }

    for (int kt = 0; kt < SEQ / 64; kt++) {
        const int k0 = kt * 64;
        __syncthreads();
#pragma unroll
        for (int t = 0; t < 4; t++) {
            int f = tid + t * 256;
            int row = f >> 4, d4 = f & 15;
            Ks[swz(row, d4)] = Kg[(k0 + row) * 16 + d4];
            Vs[swz(row, d4)] = Vg[(k0 + row) * 16 + d4];
        }
        __syncthreads();

        float s[4][4];
#pragma unroll
        for (int i = 0; i < 4; i++)
#pragma unroll
            for (int j = 0; j < 4; j++) s[i][j] = 0.f;

#pragma unroll
        for (int d4 = 0; d4 < 16; d4++) {
            float4 qv[4], kv[4];
#pragma unroll
            for (int i = 0; i < 4; i++) qv[i] = Qs[swz(ty * 4 + i, d4)];
#pragma unroll
            for (int j = 0; j < 4; j++) kv[j] = Ks[swz(tx * 4 + j, d4)];
#pragma unroll
            for (int i = 0; i < 4; i++)
#pragma unroll
                for (int j = 0; j < 4; j++)
                    s[i][j] += qv[i].x * kv[j].x + qv[i].y * kv[j].y
                             + qv[i].z * kv[j].z + qv[i].w * kv[j].w;
        }

        float p[4][4];
#pragma unroll
        for (int i = 0; i < 4; i++) {
            float rmax = fmaxf(fmaxf(s[i][0], s[i][1]), fmaxf(s[i][2], s[i][3]));
#pragma unroll
            for (int off = 8; off >= 1; off >>= 1)
                rmax = fmaxf(rmax, __shfl_xor_sync(0xffffffffu, rmax, off));
            float mnew  = fmaxf(m_prev[i], rmax);
            float alpha = __expf(m_prev[i] - mnew);
            float rsum  = 0.f;
#pragma unroll
            for (int j = 0; j < 4; j++) {
                p[i][j] = __expf(s[i][j] - mnew);
                rsum += p[i][j];
            }
#pragma unroll
            for (int off = 8; off >= 1; off >>= 1)
                rsum += __shfl_xor_sync(0xffffffffu, rsum, off);
            l[i] = l[i] * alpha + rsum;
            m_prev[i] = mnew;
            o4[i].x *= alpha; o4[i].y *= alpha; o4[i].z *= alpha; o4[i].w *= alpha;
        }

        __syncthreads();
#pragma unroll
        for (int i = 0; i < 4; i++)
            Ks[swz(ty * 4 + i, tx)] = make_float4(p[i][0], p[i][1], p[i][2], p[i][3]);
        __syncthreads();

#pragma unroll
        for (int k4 = 0; k4 < 16; k4++) {
            float4 pv[4], vv[4];
#pragma unroll
            for (int i = 0; i < 4; i++)  pv[i] = Ks[swz(ty * 4 + i, k4)];
#pragma unroll
            for (int kk = 0; kk < 4; kk++) vv[kk] = Vs[swz(k4 * 4 + kk, tx)];
#pragma unroll
            for (int i = 0; i < 4; i++) {
                o4[i].x += pv[i].x*vv[0].x + pv[i].y*vv[1].x + pv[i].z*vv[2].x + pv[i].w*vv[3].x;
                o4[i].y += pv[i].x*vv[0].y + pv[i].y*vv[1].y + pv[i].z*vv[2].y + pv[i].w*vv[3].y;
                o4[i].z += pv[i].x*vv[0].z + pv[i].y*vv[1].z + pv[i].z*vv[2].z + pv[i].w*vv[3].z;
                o4[i].w += pv[i].x*vv[0].w + pv[i].y*vv[1].w + pv[i].z*vv[2].w + pv[i].w*vv[3].w;
            }
        }
    }

#pragma unroll
    for (int i = 0; i < 4; i++) {
        float inv = 1.f / l[i];
        int q = q0 + ty * 4 + i;
        float4 v = make_float4(o4[i].x * inv, o4[i].y * inv, o4[i].z * inv, o4[i].w * inv);
        *(float4*)&O[((size_t)b * SEQ + q) * DMODEL + h * DHEAD + tx * 4] = v;
    }
}

// ---------------------------------------------------------------------------
// Launch
// ---------------------------------------------------------------------------
extern "C" void kernel_launch(void* const* d_in, const int* in_sizes, int n_in,
                              void* d_out, int out_size)
{
    const float* x  = (const float*)d_in[0];
    const float* Wq = (const float*)d_in[2];
    const float* Wk = (const float*)d_in[3];
    const float* Wv = (const float*)d_in[4];
    const float* Wp = (const float*)d_in[5];
    const float* bp = (const float*)d_in[6];
    float* out = (float*)d_out;

    float *Qp, *Kp, *Vp, *Op;
    __nv_bfloat16 *xh, *xl, *Wh, *Wl, *Oh, *Ol;
    cudaGetSymbolAddress((void**)&Qp, g_Q);
    cudaGetSymbolAddress((void**)&Kp, g_K);
    cudaGetSymbolAddress((void**)&Vp, g_V);
    cudaGetSymbolAddress((void**)&Op, g_O);
    cudaGetSymbolAddress((void**)&xh, g_xh);
    cudaGetSymbolAddress((void**)&xl, g_xl);
    cudaGetSymbolAddress((void**)&Wh, g_Wh);
    cudaGetSymbolAddress((void**)&Wl, g_Wl);
    cudaGetSymbolAddress((void**)&Oh, g_Oh);
    cudaGetSymbolAddress((void**)&Ol, g_Ol);

    constexpr int GEMM_SMEM = 2 * 4 * (128 * 144);   // 147456 B
    cudaFuncSetAttribute(mma_gemm<0>, cudaFuncAttributeMaxDynamicSharedMemorySize, GEMM_SMEM);
    cudaFuncSetAttribute(mma_gemm<1>, cudaFuncAttributeMaxDynamicSharedMemorySize, GEMM_SMEM);

    const int WSZ = DMODEL * DMODEL;
    split_kernel<<<(MROWS*DMODEL/4 + 255)/256, 256>>>((const float4*)x,
        (__nv_bfloat162*)xh, (__nv_bfloat162*)xl, MROWS*DMODEL/4);
    split_kernel<<<(WSZ/4 + 255)/256, 256>>>((const float4*)Wq,
        (__nv_bfloat162*)(Wh + 0*WSZ), (__nv_bfloat162*)(Wl + 0*WSZ), WSZ/4);
    split_kernel<<<(WSZ/4 + 255)/256, 256>>>((const float4*)Wk,
        (__nv_bfloat162*)(Wh + 1*WSZ), (__nv_bfloat162*)(Wl + 1*WSZ), WSZ/4);
    split_kernel<<<(WSZ/4 + 255)/256, 256>>>((const float4*)Wv,
        (__nv_bfloat162*)(Wh + 2*WSZ), (__nv_bfloat162*)(Wl + 2*WSZ), WSZ/4);
    split_kernel<<<(WSZ/4 + 255)/256, 256>>>((const float4*)Wp,
        (__nv_bfloat162*)(Wh + 3*WSZ), (__nv_bfloat162*)(Wl + 3*WSZ), WSZ/4);

    dim3 gg(DMODEL / 128, MROWS / 128);   // (8, 32)
    mma_gemm<1><<<gg, 256, GEMM_SMEM>>>(xh, xl, Wh + 0*WSZ, Wl + 0*WSZ, Qp, nullptr);
    mma_gemm<1><<<gg, 256, GEMM_SMEM>>>(xh, xl, Wh + 1*WSZ, Wl + 1*WSZ, Kp, nullptr);
    mma_gemm<1><<<gg, 256, GEMM_SMEM>>>(xh, xl, Wh + 2*WSZ, Wl + 2*WSZ, Vp, nullptr);

    attn_kernel<<<dim3(SEQ / 64, HEADS, BATCH), 256>>>(Op);

    split_kernel<<<(MROWS*DMODEL/4 + 255)/256, 256>>>((const float4*)Op,
        (__nv_bfloat162*)Oh, (__nv_bfloat162*)Ol, MROWS*DMODEL/4);
    mma_gemm<0><<<gg, 256, GEMM_SMEM>>>(Oh, Ol, Wh + 3*WSZ, Wl + 3*WSZ, out, bp);
}

// round 5
// speedup vs baseline: 3.3926x; 2.4673x over previous
#include <cuda_runtime.h>
#include <cuda_bf16.h>
#include <cuda_fp16.h>
#include <math_constants.h>
#include <cstdint>

#define SEQ    2048
#define BATCH  2
#define HEADS  16
#define DHEAD  64
#define DMODEL 1024
#define MROWS  (BATCH*SEQ)   // 4096
#define LOG2E  1.4426950408889634f

// ---------------------------------------------------------------------------
// Scratch (__device__ globals: allocation-free rule)
// ---------------------------------------------------------------------------
__device__ float g_O[BATCH*SEQ*DMODEL];
__device__ __half g_qh[BATCH*HEADS*SEQ*DHEAD], g_ql[BATCH*HEADS*SEQ*DHEAD];
__device__ __half g_kh[BATCH*HEADS*SEQ*DHEAD], g_kl[BATCH*HEADS*SEQ*DHEAD];
__device__ __half g_vh[BATCH*HEADS*SEQ*DHEAD];
__device__ __nv_bfloat16 g_xh[MROWS*DMODEL], g_xl[MROWS*DMODEL];
__device__ __nv_bfloat16 g_Wh[4*DMODEL*DMODEL], g_Wl[4*DMODEL*DMODEL]; // q,k,v,p
__device__ __nv_bfloat16 g_Oh[MROWS*DMODEL], g_Ol[MROWS*DMODEL];

// ---------------------------------------------------------------------------
// PTX helpers (compute_103-safe: cp.async + ldmatrix + mma.sync)
// ---------------------------------------------------------------------------
__device__ __forceinline__ uint32_t smem_u32(const void* p) {
    uint32_t a;
    asm("{ .reg .u64 t; cvta.to.shared.u64 t, %1; cvt.u32.u64 %0, t; }" : "=r"(a) : "l"(p));
    return a;
}
#define CP16(dst, src)  asm volatile("cp.async.cg.shared.global [%0], [%1], 16;" :: "r"(dst), "l"(src))
#define CP_COMMIT()     asm volatile("cp.async.commit_group;" ::: "memory")
#define CP_WAIT0()      asm volatile("cp.async.wait_group 0;" ::: "memory")
#define CP_WAIT1()      asm volatile("cp.async.wait_group 1;" ::: "memory")

__device__ __forceinline__ void ldm_x4(uint32_t (&r)[4], uint32_t addr) {
    asm volatile("ldmatrix.sync.aligned.m8n8.x4.shared.b16 {%0,%1,%2,%3}, [%4];"
        : "=r"(r[0]), "=r"(r[1]), "=r"(r[2]), "=r"(r[3]) : "r"(addr));
}
__device__ __forceinline__ void ldm_x2(uint32_t (&r)[2], uint32_t addr) {
    asm volatile("ldmatrix.sync.aligned.m8n8.x2.shared.b16 {%0,%1}, [%2];"
        : "=r"(r[0]), "=r"(r[1]) : "r"(addr));
}
__device__ __forceinline__ void ldm_x2t(uint32_t (&r)[2], uint32_t addr) {
    asm volatile("ldmatrix.sync.aligned.m8n8.x2.trans.shared.b16 {%0,%1}, [%2];"
        : "=r"(r[0]), "=r"(r[1]) : "r"(addr));
}
__device__ __forceinline__ void mma_bf16(float (&c)[4], const uint32_t (&a)[4], const uint32_t (&b)[2]) {
    asm volatile("mma.sync.aligned.m16n8k16.row.col.f32.bf16.bf16.f32 "
        "{%0,%1,%2,%3}, {%4,%5,%6,%7}, {%8,%9}, {%0,%1,%2,%3};"
        : "+f"(c[0]), "+f"(c[1]), "+f"(c[2]), "+f"(c[3])
        : "r"(a[0]), "r"(a[1]), "r"(a[2]), "r"(a[3]), "r"(b[0]), "r"(b[1]));
}
__device__ __forceinline__ void mma_fp16(float (&c)[4], const uint32_t (&a)[4], const uint32_t (&b)[2]) {
    asm volatile("mma.sync.aligned.m16n8k16.row.col.f32.f16.f16.f32 "
        "{%0,%1,%2,%3}, {%4,%5,%6,%7}, {%8,%9}, {%0,%1,%2,%3};"
        : "+f"(c[0]), "+f"(c[1]), "+f"(c[2]), "+f"(c[3])
        : "r"(a[0]), "r"(a[1]), "r"(a[2]), "r"(a[3]), "r"(b[0]), "r"(b[1]));
}
__device__ __forceinline__ uint32_t packh2(float x, float y) {
    __half2 h = __floats2half2_rn(x, y);
    return *reinterpret_cast<uint32_t*>(&h);
}
// Fast 2^y on the FMA pipe (y <= 0, clamped; ~2.4e-6 rel err)
__device__ __forceinline__ float exp2_fast(float y) {
    y = fmaxf(y, -100.f);
    float z = y + 12582912.f;                 // 1.5*2^23: RN-to-int in low bits
    int   e = __float_as_int(z) << 23;        // n << 23
    float f = y - (z - 12582912.f);           // f in [-0.5, 0.5]
    float p =            1.3333558e-3f;
    p = fmaf(p, f, 9.6181291e-3f);
    p = fmaf(p, f, 5.5504109e-2f);
    p = fmaf(p, f, 2.4022651e-1f);
    p = fmaf(p, f, 6.9314718e-1f);
    p = fmaf(p, f, 1.0f);
    return __int_as_float(__float_as_int(p) + e);
}

// ---------------------------------------------------------------------------
// Split fp32 -> (bf16 hi, bf16 lo)
// ---------------------------------------------------------------------------
__global__ void split_kernel(const float4* __restrict__ in, __nv_bfloat162* __restrict__ hi,
                             __nv_bfloat162* __restrict__ lo, int n4)
{
    int i = blockIdx.x * blockDim.x + threadIdx.x;
    if (i >= n4) return;
    float4 v = in[i];
    __nv_bfloat162 h0 = __floats2bfloat162_rn(v.x, v.y);
    __nv_bfloat162 h1 = __floats2bfloat162_rn(v.z, v.w);
    hi[2*i]   = h0;
    hi[2*i+1] = h1;
    float rx = v.x - __bfloat162float(h0.x);
    float ry = v.y - __bfloat162float(h0.y);
    float rz = v.z - __bfloat162float(h1.x);
    float rw = v.w - __bfloat162float(h1.y);
    lo[2*i]   = __floats2bfloat162_rn(rx, ry);
    lo[2*i+1] = __floats2bfloat162_rn(rz, rw);
}

// ---------------------------------------------------------------------------
// mma.sync split-bf16 GEMM: C[M,N] = A[M,K] @ B[N,K]^T (fp32-grade accuracy)
// MODE 0: float C += bias, [r][c]
// MODE 2: fp16 hi/lo pair scattered into [B,H,S,Dh] (for Q, K)
// MODE 3: fp16 single scattered into [B,H,S,Dh]     (for V)
// ---------------------------------------------------------------------------
template<int MODE>
__global__ __launch_bounds__(256)
void mma_gemm(const __nv_bfloat16* __restrict__ Ah, const __nv_bfloat16* __restrict__ Al,
              const __nv_bfloat16* __restrict__ Bh, const __nv_bfloat16* __restrict__ Bl,
              void* __restrict__ out0, void* __restrict__ out1, const float* __restrict__ bias)
{
    constexpr int K = DMODEL;
    constexpr int BK = 64;
    constexpr int NCHUNK = K / BK;            // 16
    constexpr int RSTRIDE = 144;
    constexpr int TILE = 128 * RSTRIDE;
    constexpr int STAGE = 4 * TILE;

    extern __shared__ __align__(128) char smem[];
    const uint32_t sb = smem_u32(smem);
    const int tid  = threadIdx.x;
    const int wid  = tid >> 5;
    const int lane = tid & 31;
    const int warp_m = wid & 1;
    const int warp_n = wid >> 1;
    const int bm = blockIdx.y * 128;
    const int bn = blockIdx.x * 128;

    const uint32_t aoff = (uint32_t)(warp_m * 64 + (lane & 15)) * RSTRIDE + (uint32_t)(lane >> 4) * 16;
    const uint32_t boff = (uint32_t)(warp_n * 32 + (lane & 7))  * RSTRIDE + (uint32_t)((lane >> 3) & 1) * 16;

    float acc[4][4][4];
#pragma unroll
    for (int mi = 0; mi < 4; mi++)
#pragma unroll
        for (int ni = 0; ni < 4; ni++)
#pragma unroll
            for (int j = 0; j < 4; j++) acc[mi][ni][j] = 0.f;

    auto load_chunk = [&](int i) {
        uint32_t base = sb + (uint32_t)(i & 1) * STAGE;
        int k0 = i * BK;
#pragma unroll
        for (int t = 0; t < 4; t++) {
            int c   = tid + t * 256;
            int row = c >> 3, kk = c & 7;
            uint32_t so = (uint32_t)row * RSTRIDE + (uint32_t)kk * 16;
            size_t ao = (size_t)(bm + row) * K + k0 + kk * 8;
            size_t bo = (size_t)(bn + row) * K + k0 + kk * 8;
            CP16(base + so,            Ah + ao);
            CP16(base + TILE + so,     Al + ao);
            CP16(base + 2*TILE + so,   Bh + bo);
            CP16(base + 3*TILE + so,   Bl + bo);
        }
    };

    load_chunk(0);
    CP_COMMIT();

    for (int i = 0; i < NCHUNK; i++) {
        if (i + 1 < NCHUNK) { load_chunk(i + 1); CP_COMMIT(); CP_WAIT1(); }
        else                { CP_WAIT0(); }
        __syncthreads();

        uint32_t base = sb + (uint32_t)(i & 1) * STAGE;
#pragma unroll
        for (int ks = 0; ks < 4; ks++) {
            const uint32_t koff = (uint32_t)ks * 32;
            uint32_t bh[4][2], bl[4][2];
#pragma unroll
            for (int ni = 0; ni < 4; ni++) {
                uint32_t ba = base + boff + (uint32_t)ni * 8 * RSTRIDE + koff;
                ldm_x2(bh[ni], ba + 2*TILE);
                ldm_x2(bl[ni], ba + 3*TILE);
            }
            uint32_t af[4][4];
#pragma unroll
            for (int mi = 0; mi < 4; mi++)
                ldm_x4(af[mi], base + aoff + (uint32_t)mi * 16 * RSTRIDE + koff);
#pragma unroll
            for (int mi = 0; mi < 4; mi++)
#pragma unroll
                for (int ni = 0; ni < 4; ni++) mma_bf16(acc[mi][ni], af[mi], bh[ni]);
#pragma unroll
            for (int mi = 0; mi < 4; mi++)
#pragma unroll
                for (int ni = 0; ni < 4; ni++) mma_bf16(acc[mi][ni], af[mi], bl[ni]);
#pragma unroll
            for (int mi = 0; mi < 4; mi++)
                ldm_x4(af[mi], base + TILE + aoff + (uint32_t)mi * 16 * RSTRIDE + koff);
#pragma unroll
            for (int mi = 0; mi < 4; mi++)
#pragma unroll
                for (int ni = 0; ni < 4; ni++) mma_bf16(acc[mi][ni], af[mi], bh[ni]);
        }
        __syncthreads();
    }

    const int rbase = bm + warp_m * 64 + (lane >> 2);
    const int cbase = bn + warp_n * 32 + 2 * (lane & 3);
#pragma unroll
    for (int mi = 0; mi < 4; mi++) {
#pragma unroll
        for (int ni = 0; ni < 4; ni++) {
            int c = cbase + ni * 8;
#pragma unroll
            for (int half = 0; half < 2; half++) {
                int r = rbase + mi * 16 + half * 8;
                float2 v = make_float2(acc[mi][ni][2*half], acc[mi][ni][2*half + 1]);
                if (MODE == 0) {
                    v.x += bias[c]; v.y += bias[c + 1];
                    *(float2*)&((float*)out0)[(size_t)r * DMODEL + c] = v;
                } else {
                    int b = r >> 11, s2 = r & 2047;
                    int h = c >> 6,  d = c & 63;
                    size_t idx = (((size_t)(b * HEADS + h)) * SEQ + s2) * DHEAD + d;
                    __half hx = __float2half_rn(v.x), hy = __float2half_rn(v.y);
                    *(__half2*)((__half*)out0 + idx) = __halves2half2(hx, hy);
                    if (MODE == 2) {
                        __half lx = __float2half_rn(v.x - __half2float(hx));
                        __half ly = __float2half_rn(v.y - __half2float(hy));
                        *(__half2*)((__half*)out1 + idx) = __halves2half2(lx, ly);
                    }
                }
            }
        }
    }
}

// ---------------------------------------------------------------------------
// Tensor-core flash attention. CTA = (b, h, 128 queries), 8 warps x 16 rows.
// QK^T: split-fp16 3-term; softmax: FFMA-pipe exp2; PV: single fp16.
// Smem tiles: 128B rows, chunk c stored at c^(r&7) (conflict-free ldmatrix).
// ---------------------------------------------------------------------------
__global__ __launch_bounds__(256, 2)
void attn_tc(float* __restrict__ O)
{
    extern __shared__ __align__(128) char sm[];
    const uint32_t sb = smem_u32(sm);
    constexpr uint32_t QH = 0, QL = 16384, ST = 32768, STSZ = 24576;
    constexpr uint32_t KHO = 0, KLO = 8192, VHO = 16384;

    const int tid = threadIdx.x, wid = tid >> 5, lane = tid & 31;
    const int q0 = blockIdx.x * 128, h = blockIdx.y, b = blockIdx.z;
    const size_t hb = ((size_t)(b * HEADS + h)) * SEQ;
    const __half* qhp = g_qh + (hb + q0) * DHEAD;
    const __half* qlp = g_ql + (hb + q0) * DHEAD;
    const __half* khp = g_kh + hb * DHEAD;
    const __half* klp = g_kl + hb * DHEAD;
    const __half* vhp = g_vh + hb * DHEAD;

    auto load_stage = [&](int kt) {
        uint32_t base = sb + ST + (uint32_t)(kt & 1) * STSZ;
#pragma unroll
        for (int t = 0; t < 6; t++) {
            int idx = tid + t * 256;          // 0..1535
            int tile = idx >> 9;              // 0:kh 1:kl 2:vh
            int r = (idx >> 3) & 63, c = idx & 7;
            uint32_t sw = (uint32_t)r * 128 + (uint32_t)((c ^ (r & 7)) * 16);
            const __half* src = (tile == 0 ? khp : tile == 1 ? klp : vhp)
                                + (size_t)(kt * 64 + r) * DHEAD + c * 8;
            CP16(base + (uint32_t)tile * 8192 + sw, src);
        }
    };

    // Q (hi+lo) into smem
#pragma unroll
    for (int t = 0; t < 8; t++) {
        int idx = tid + t * 256;              // 0..2047
        int tile = idx >> 10;
        int r = (idx >> 3) & 127, c = idx & 7;
        uint32_t dst = sb + (tile ? QL : QH) + (uint32_t)r * 128 + (uint32_t)((c ^ (r & 7)) * 16);
        const __half* src = (tile ? qlp : qhp) + (size_t)r * DHEAD + c * 8;
        CP16(dst, src);
    }
    load_stage(0);
    CP_COMMIT();

    float s[8][4], o[8][4];
#pragma unroll
    for (int j = 0; j < 8; j++)
#pragma unroll
        for (int r = 0; r < 4; r++) o[j][r] = 0.f;
    float m2_0 = -1e30f, m2_1 = -1e30f, l0 = 0.f, l1 = 0.f;
    uint32_t aqh[4][4];

    const int ar = wid * 16 + (lane & 15);
    const int kr = lane & 7, kc = (lane >> 3) & 1;

    for (int kt = 0; kt < SEQ / 64; kt++) {
        if (kt + 1 < SEQ / 64) { load_stage(kt + 1); CP_COMMIT(); CP_WAIT1(); }
        else                   { CP_WAIT0(); }
        __syncthreads();
        uint32_t kb = sb + ST + (uint32_t)(kt & 1) * STSZ;

        if (kt == 0) {
#pragma unroll
            for (int ks = 0; ks < 4; ks++) {
                int c = 2 * ks + (lane >> 4);
                ldm_x4(aqh[ks], sb + QH + (uint32_t)ar * 128 + (uint32_t)((c ^ (ar & 7)) * 16));
            }
        }

        // ---- S = Q K^T (3-term split fp16) ----
#pragma unroll
        for (int j = 0; j < 8; j++)
#pragma unroll
            for (int r = 0; r < 4; r++) s[j][r] = 0.f;

#pragma unroll
        for (int ks = 0; ks < 4; ks++) {
            uint32_t aql[4];
            {
                int c = 2 * ks + (lane >> 4);
                ldm_x4(aql, sb + QL + (uint32_t)ar * 128 + (uint32_t)((c ^ (ar & 7)) * 16));
            }
#pragma unroll
            for (int j = 0; j < 8; j++) {
                uint32_t bh[2], bl[2];
                int r = j * 8 + kr, c = 2 * ks + kc;
                uint32_t sw = (uint32_t)r * 128 + (uint32_t)((c ^ (r & 7)) * 16);
                ldm_x2(bh, kb + KHO + sw);
                ldm_x2(bl, kb + KLO + sw);
                mma_fp16(s[j], aqh[ks], bh);
                mma_fp16(s[j], aqh[ks], bl);
                mma_fp16(s[j], aql,     bh);
            }
        }

        // ---- online softmax (rows r0 = lane>>2, r1 = r0+8) ----
        float mx0 = -1e30f, mx1 = -1e30f;
#pragma unroll
        for (int j = 0; j < 8; j++) {
            mx0 = fmaxf(mx0, fmaxf(s[j][0], s[j][1]));
            mx1 = fmaxf(mx1, fmaxf(s[j][2], s[j][3]));
        }
        mx0 = fmaxf(mx0, __shfl_xor_sync(0xffffffffu, mx0, 1));
        mx0 = fmaxf(mx0, __shfl_xor_sync(0xffffffffu, mx0, 2));
        mx1 = fmaxf(mx1, __shfl_xor_sync(0xffffffffu, mx1, 1));
        mx1 = fmaxf(mx1, __shfl_xor_sync(0xffffffffu, mx1, 2));
        float m2n0 = fmaxf(m2_0, mx0 * LOG2E);
        float m2n1 = fmaxf(m2_1, mx1 * LOG2E);
        float al0 = exp2_fast(m2_0 - m2n0);
        float al1 = exp2_fast(m2_1 - m2n1);
        m2_0 = m2n0; m2_1 = m2n1;
        float sm0 = 0.f, sm1 = 0.f;
#pragma unroll
        for (int j = 0; j < 8; j++) {
            s[j][0] = exp2_fast(fmaf(s[j][0], LOG2E, -m2_0)); sm0 += s[j][0];
            s[j][1] = exp2_fast(fmaf(s[j][1], LOG2E, -m2_0)); sm0 += s[j][1];
            s[j][2] = exp2_fast(fmaf(s[j][2], LOG2E, -m2_1)); sm1 += s[j][2];
            s[j][3] = exp2_fast(fmaf(s[j][3], LOG2E, -m2_1)); sm1 += s[j][3];
        }
        sm0 += __shfl_xor_sync(0xffffffffu, sm0, 1);
        sm0 += __shfl_xor_sync(0xffffffffu, sm0, 2);
        sm1 += __shfl_xor_sync(0xffffffffu, sm1, 1);
        sm1 += __shfl_xor_sync(0xffffffffu, sm1, 2);
        l0 = l0 * al0 + sm0;
        l1 = l1 * al1 + sm1;
#pragma unroll
        for (int j = 0; j < 8; j++) {
            o[j][0] *= al0; o[j][1] *= al0; o[j][2] *= al1; o[j][3] *= al1;
        }

        // ---- O += P V (single fp16; S-frags reused as A-frags) ----
#pragma unroll
        for (int ks = 0; ks < 4; ks++) {
            uint32_t a[4];
            a[0] = packh2(s[2*ks][0],   s[2*ks][1]);
            a[1] = packh2(s[2*ks][2],   s[2*ks][3]);
            a[2] = packh2(s[2*ks+1][0], s[2*ks+1][1]);
            a[3] = packh2(s[2*ks+1][2], s[2*ks+1][3]);
#pragma unroll
            for (int j = 0; j < 8; j++) {
                uint32_t bv[2];
                int r = ks * 16 + (lane & 15), c = j;
                ldm_x2t(bv, kb + VHO + (uint32_t)r * 128 + (uint32_t)((c ^ (r & 7)) * 16));
                mma_fp16(o[j], a, bv);
            }
        }
        __syncthreads();
    }

    // ---- normalize + store [B,S,D] ----
    float inv0 = 1.f / l0, inv1 = 1.f / l1;
    int r0 = q0 + wid * 16 + (lane >> 2);
    int colb = h * DHEAD + 2 * (lane & 3);
#pragma unroll
    for (int j = 0; j < 8; j++) {
        float2 v0 = make_float2(o[j][0] * inv0, o[j][1] * inv0);
        float2 v1 = make_float2(o[j][2] * inv1, o[j][3] * inv1);
        *(float2*)&O[((size_t)b * SEQ + r0)     * DMODEL + colb + 8*j] = v0;
        *(float2*)&O[((size_t)b * SEQ + r0 + 8) * DMODEL + colb + 8*j] = v1;
    }
}

// ---------------------------------------------------------------------------
// Launch
// ---------------------------------------------------------------------------
extern "C" void kernel_launch(void* const* d_in, const int* in_sizes, int n_in,
                              void* d_out, int out_size)
{
    const float* x  = (const float*)d_in[0];
    const float* Wq = (const float*)d_in[2];
    const float* Wk = (const float*)d_in[3];
    const float* Wv = (const float*)d_in[4];
    const float* Wp = (const float*)d_in[5];
    const float* bp = (const float*)d_in[6];
    float* out = (float*)d_out;

    float* Op;
    __half *qh, *ql, *kh, *kl, *vh;
    __nv_bfloat16 *xh, *xl, *Wh, *Wl, *Oh, *Ol;
    cudaGetSymbolAddress((void**)&Op, g_O);
    cudaGetSymbolAddress((void**)&qh, g_qh);
    cudaGetSymbolAddress((void**)&ql, g_ql);
    cudaGetSymbolAddress((void**)&kh, g_kh);
    cudaGetSymbolAddress((void**)&kl, g_kl);
    cudaGetSymbolAddress((void**)&vh, g_vh);
    cudaGetSymbolAddress((void**)&xh, g_xh);
    cudaGetSymbolAddress((void**)&xl, g_xl);
    cudaGetSymbolAddress((void**)&Wh, g_Wh);
    cudaGetSymbolAddress((void**)&Wl, g_Wl);
    cudaGetSymbolAddress((void**)&Oh, g_Oh);
    cudaGetSymbolAddress((void**)&Ol, g_Ol);

    constexpr int GEMM_SMEM = 2 * 4 * (128 * 144);   // 147456 B
    constexpr int ATTN_SMEM = 32768 + 2 * 24576;     // 81920 B
    cudaFuncSetAttribute(mma_gemm<0>, cudaFuncAttributeMaxDynamicSharedMemorySize, GEMM_SMEM);
    cudaFuncSetAttribute(mma_gemm<2>, cudaFuncAttributeMaxDynamicSharedMemorySize, GEMM_SMEM);
    cudaFuncSetAttribute(mma_gemm<3>, cudaFuncAttributeMaxDynamicSharedMemorySize, GEMM_SMEM);
    cudaFuncSetAttribute(attn_tc,     cudaFuncAttributeMaxDynamicSharedMemorySize, ATTN_SMEM);

    const int WSZ = DMODEL * DMODEL;
    split_kernel<<<(MROWS*DMODEL/4 + 255)/256, 256>>>((const float4*)x,
        (__nv_bfloat162*)xh, (__nv_bfloat162*)xl, MROWS*DMODEL/4);
    split_kernel<<<(WSZ/4 + 255)/256, 256>>>((const float4*)Wq,
        (__nv_bfloat162*)(Wh + 0*WSZ), (__nv_bfloat162*)(Wl + 0*WSZ), WSZ/4);
    split_kernel<<<(WSZ/4 + 255)/256, 256>>>((const float4*)Wk,
        (__nv_bfloat162*)(Wh + 1*WSZ), (__nv_bfloat162*)(Wl + 1*WSZ), WSZ/4);
    split_kernel<<<(WSZ/4 + 255)/256, 256>>>((const float4*)Wv,
        (__nv_bfloat162*)(Wh + 2*WSZ), (__nv_bfloat162*)(Wl + 2*WSZ), WSZ/4);
    split_kernel<<<(WSZ/4 + 255)/256, 256>>>((const float4*)Wp,
        (__nv_bfloat162*)(Wh + 3*WSZ), (__nv_bfloat162*)(Wl + 3*WSZ), WSZ/4);

    dim3 gg(DMODEL / 128, MROWS / 128);   // (8, 32)
    mma_gemm<2><<<gg, 256, GEMM_SMEM>>>(xh, xl, Wh + 0*WSZ, Wl + 0*WSZ, qh, ql, nullptr);
    mma_gemm<2><<<gg, 256, GEMM_SMEM>>>(xh, xl, Wh + 1*WSZ, Wl + 1*WSZ, kh, kl, nullptr);
    mma_gemm<3><<<gg, 256, GEMM_SMEM>>>(xh, xl, Wh + 2*WSZ, Wl + 2*WSZ, vh, nullptr, nullptr);

    attn_tc<<<dim3(SEQ / 128, HEADS, BATCH), 256, ATTN_SMEM>>>(Op);

    split_kernel<<<(MROWS*DMODEL/4 + 255)/256, 256>>>((const float4*)Op,
        (__nv_bfloat162*)Oh, (__nv_bfloat162*)Ol, MROWS*DMODEL/4);
    mma_gemm<0><<<gg, 256, GEMM_SMEM>>>(Oh, Ol, Wh + 3*WSZ, Wl + 3*WSZ, out, nullptr, bp);
}